// round 7
// baseline (speedup 1.0000x reference)
#include <cuda_runtime.h>
#include <cstdint>

// Net_60413009985719 — collapsed net (no recurrence, only x[L-1] matters,
// LSTM f-gate dead). R7 = R4 base with the SMEM crossbar cost attacked:
//  - W rows padded to 68 floats: conflict-free LDS.128 WITHOUT rotation
//  - h read with uniform index -> smem BROADCAST (4 phases -> 1 per load)
//  - per-row TMA copies (256B) issued in parallel by 192 threads
//  - __expf activations (shorter MUFU chain on the x5 serial act path)

#define H 64
#define ROWS 192          // live gate rows per layer (i, g, o; f is dead)
#define WPAD 68           // padded row stride in floats (272B, 16B-aligned)
#define NT 512

// ---- shared layout (float offsets) ----
#define OFF_W    0                        // [4][192][68] padded rows
#define OFF_FC   (OFF_W + 4*ROWS*WPAD)    // [32][64] contiguous
#define OFF_W0   (OFF_FC + 32*H)          // [192]
#define OFF_B0   (OFF_W0 + ROWS)          // [192]
#define OFF_BS   (OFF_B0 + ROWS)          // [4][192]
#define OFF_C1W  (OFF_BS + 4*ROWS)        // [16][32]
#define OFF_C1B  (OFF_C1W + 512)          // [16]
#define OFF_FCB  (OFF_C1B + 16)           // [32]
#define OFF_MW   (OFF_FCB + 32)           // [32]
#define OFF_LSW  (OFF_MW + 32)            // [32]
#define OFF_C2W  (OFF_LSW + 32)           // [16]
#define OFF_SC   (OFF_C2W + 16)           // [3]
#define OFF_H    (((OFF_SC + 3) + 3) & ~3)    // [64], 16B-aligned
#define OFF_G    (OFF_H + H)              // [192]
#define OFF_Z    (OFF_G + ROWS)           // [32]
#define OFF_VH   (OFF_Z + 32)             // [16]
#define OFF_SCAL (OFF_VH + 16)            // [2]
#define OFF_MBAR (((OFF_SCAL + 2) + 1) & ~1)  // 8B-aligned; 5 x u64
#define SMEM_FLOATS (OFF_MBAR + 10)
#define SMEM_BYTES  (SMEM_FLOATS * 4)

static_assert(SMEM_BYTES <= 227 * 1024, "exceeds sm_100a dynamic smem");
static_assert((WPAD % 4) == 0, "padded stride must be 16B-aligned");
static_assert((OFF_H % 4) == 0, "h vector must be 16B-aligned");
static_assert((OFF_FC % 4) == 0, "fc rows must be 16B-aligned");
static_assert((OFF_MBAR % 2) == 0, "mbarrier must be 8B-aligned");

__device__ __forceinline__ float fsig(float x) {
    return __fdividef(1.0f, 1.0f + __expf(-x));
}
__device__ __forceinline__ float ftanh(float x) {
    float ax = fabsf(x);
    float e  = __expf(-2.0f * ax);
    float t  = __fdividef(1.0f - e, 1.0f + e);
    return copysignf(t, x);
}

__device__ __forceinline__ void mbar_init(uint32_t addr, uint32_t count) {
    asm volatile("mbarrier.init.shared.b64 [%0], %1;" :: "r"(addr), "r"(count) : "memory");
}
__device__ __forceinline__ void mbar_expect(uint32_t addr, uint32_t bytes) {
    asm volatile("mbarrier.arrive.expect_tx.shared.b64 _, [%0], %1;"
                 :: "r"(addr), "r"(bytes) : "memory");
}
__device__ __forceinline__ void bulk_g2s(uint32_t dst, const void* src,
                                         uint32_t bytes, uint32_t mbar) {
    asm volatile("cp.async.bulk.shared::cta.global.mbarrier::complete_tx::bytes "
                 "[%0], [%1], %2, [%3];"
                 :: "r"(dst), "l"(src), "r"(bytes), "r"(mbar) : "memory");
}
__device__ __forceinline__ void mbar_wait0(uint32_t addr) {
    asm volatile(
        "{\n\t"
        ".reg .pred P;\n\t"
        "WAIT_%=:\n\t"
        "mbarrier.try_wait.parity.acquire.cta.shared::cta.b64 P, [%0], 0, 0x989680;\n\t"
        "@P bra.uni DONE_%=;\n\t"
        "bra.uni WAIT_%=;\n\t"
        "DONE_%=:\n\t"
        "}" :: "r"(addr) : "memory");
}
__device__ __forceinline__ void fence_proxy_async_sc() {
    asm volatile("fence.proxy.async.shared::cta;" ::: "memory");
}

__device__ __forceinline__ void do_act(float* sm, int idx) {
    float iv = fsig(sm[OFF_G + idx]);
    float gv = ftanh(sm[OFF_G + 64 + idx]);
    float ov = fsig(sm[OFF_G + 128 + idx]);
    sm[OFF_H + idx] = ov * ftanh(iv * gv);
}

__global__ void __launch_bounds__(NT, 1)
net_kernel(const float* __restrict__ x, long long L,
           const float* __restrict__ Wih0,
           const float* __restrict__ bih0,
           const float* __restrict__ bhh0,
           const float* __restrict__ Wih,
           const float* __restrict__ bih,
           const float* __restrict__ bhh,
           const float* __restrict__ fc_w,
           const float* __restrict__ fc_b,
           const float* __restrict__ mean_w,
           const float* __restrict__ mean_b,
           const float* __restrict__ ls_w,
           const float* __restrict__ ls_b,
           const float* __restrict__ c1_w,
           const float* __restrict__ c1_b,
           const float* __restrict__ c2_w,
           const float* __restrict__ c2_b,
           float* __restrict__ out)
{
    extern __shared__ __align__(16) float sm[];
    const int tid = threadIdx.x;
    const uint32_t smbase = (uint32_t)__cvta_generic_to_shared(sm);
    const uint32_t mbar = smbase + OFF_MBAR * 4;

    // ---- 0) mbarrier init, then parallel per-row TMA issue ----
    if (tid == 0) {
        #pragma unroll
        for (int i = 0; i < 5; ++i) mbar_init(mbar + 8 * i, 1);
        fence_proxy_async_sc();
        #pragma unroll
        for (int l = 0; l < 4; ++l)
            mbar_expect(mbar + 8 * l, ROWS * H * 4);       // 192 rows x 256B
        mbar_expect(mbar + 8 * 4, 32 * H * 4);             // fc 8KB
    }
    const float xv = x[L - 1];     // issue the one live input load early
    __syncthreads();               // barriers initialized + visible

    if (tid < ROWS) {
        int grow = (tid < 64) ? tid : tid + 64;            // skip dead f rows
        #pragma unroll
        for (int l = 0; l < 4; ++l) {                      // layer 1 rows first
            bulk_g2s(smbase + (OFF_W + (l * ROWS + tid) * WPAD) * 4,
                     Wih + ((size_t)l * 256 + grow) * H, H * 4, mbar + 8 * l);
        }
    } else if (tid == 192) {
        bulk_g2s(smbase + OFF_FC * 4, fc_w, 32 * H * 4, mbar + 8 * 4);
    }

    // ---- 1) stage small tensors (coalesced LDG->STS, overlaps TMA flight) ----
    if (tid < ROWS) {
        int grow = (tid < 64) ? tid : tid + 64;
        sm[OFF_W0 + tid] = Wih0[grow];
        sm[OFF_B0 + tid] = bih0[grow] + bhh0[grow];
    }
    for (int j = tid; j < 4 * ROWS; j += NT) {
        int l = j / ROWS, r = j - l * ROWS;
        int grow = (r < 64) ? r : r + 64;
        sm[OFF_BS + j] = bih[l * 256 + grow] + bhh[l * 256 + grow];
    }
    for (int j = tid; j < 512; j += NT) sm[OFF_C1W + j] = c1_w[j];
    if (tid < 32) {
        sm[OFF_FCB + tid] = fc_b[tid];
        sm[OFF_MW + tid]  = mean_w[tid];
        sm[OFF_LSW + tid] = ls_w[tid];
    }
    if (tid < 16) {
        sm[OFF_C1B + tid] = c1_b[tid];
        sm[OFF_C2W + tid] = c2_w[tid];
    }
    if (tid == 193) {
        sm[OFF_SC + 0] = mean_b[0];
        sm[OFF_SC + 1] = ls_b[0];
        sm[OFF_SC + 2] = c2_b[0];
    }
    __syncthreads();

    // ---- 2) layer 0: gates from scalar, then activation ----
    if (tid < ROWS) sm[OFF_G + tid] = xv * sm[OFF_W0 + tid] + sm[OFF_B0 + tid];
    __syncthreads();
    if (tid < H) do_act(sm, tid);

    // ---- 3) layers 1..4: padded-W conflict-free LDS + broadcast h ----
    #pragma unroll
    for (int l = 0; l < 4; ++l) {
        mbar_wait0(mbar + 8 * l);
        __syncthreads();       // TMA layer data + h visible
        if (tid < ROWS) {
            const float4* Wr = (const float4*)(sm + OFF_W + (l * ROWS + tid) * WPAD);
            const float4* hv = (const float4*)(sm + OFF_H);
            float a0 = 0.f, a1 = 0.f, a2 = 0.f, a3 = 0.f;
            #pragma unroll
            for (int j = 0; j < 16; j += 4) {
                // uniform j: h loads broadcast (1 phase); W conflict-free via pad
                float4 w0 = Wr[j + 0], h0 = hv[j + 0];
                float4 w1 = Wr[j + 1], h1 = hv[j + 1];
                float4 w2 = Wr[j + 2], h2 = hv[j + 2];
                float4 w3 = Wr[j + 3], h3 = hv[j + 3];
                a0 += w0.x * h0.x + w0.y * h0.y + w0.z * h0.z + w0.w * h0.w;
                a1 += w1.x * h1.x + w1.y * h1.y + w1.z * h1.z + w1.w * h1.w;
                a2 += w2.x * h2.x + w2.y * h2.y + w2.z * h2.z + w2.w * h2.w;
                a3 += w3.x * h3.x + w3.y * h3.y + w3.z * h3.z + w3.w * h3.w;
            }
            sm[OFF_G + tid] = (a0 + a1) + (a2 + a3) + sm[OFF_BS + l * ROWS + tid];
        }
        __syncthreads();
        if (tid < H) do_act(sm, tid);
    }

    mbar_wait0(mbar + 8 * 4);  // fc weights
    __syncthreads();

    // ---- 4) head: z = relu(fc) — contiguous rows, rotation as in R4 ----
    if (tid < 32) {
        const float4* Wr = (const float4*)(sm + OFF_FC + tid * H);
        const float4* hv = (const float4*)(sm + OFF_H);
        float a0 = 0.f, a1 = 0.f, a2 = 0.f, a3 = 0.f;
        #pragma unroll
        for (int j = 0; j < 16; j += 4) {
            int k0 = (j + 0 + tid) & 15;
            int k1 = (j + 1 + tid) & 15;
            int k2 = (j + 2 + tid) & 15;
            int k3 = (j + 3 + tid) & 15;
            float4 w0 = Wr[k0], h0 = hv[k0];
            float4 w1 = Wr[k1], h1 = hv[k1];
            float4 w2 = Wr[k2], h2 = hv[k2];
            float4 w3 = Wr[k3], h3 = hv[k3];
            a0 += w0.x * h0.x + w0.y * h0.y + w0.z * h0.z + w0.w * h0.w;
            a1 += w1.x * h1.x + w1.y * h1.y + w1.z * h1.z + w1.w * h1.w;
            a2 += w2.x * h2.x + w2.y * h2.y + w2.z * h2.z + w2.w * h2.w;
            a3 += w3.x * h3.x + w3.y * h3.y + w3.z * h3.z + w3.w * h3.w;
        }
        sm[OFF_Z + tid] = fmaxf((a0 + a1) + (a2 + a3) + sm[OFF_FCB + tid], 0.0f);
    }
    __syncthreads();

    // ---- 5) tiny heads ----
    if (tid < 16) {
        const float* Wr = sm + OFF_C1W + tid * 32;
        float a0 = 0.f, a1 = 0.f, a2 = 0.f, a3 = 0.f;
        #pragma unroll
        for (int k = 0; k < 32; k += 4) {
            int k0 = (k + 0 + 2 * tid) & 31;
            int k1 = (k + 1 + 2 * tid) & 31;
            int k2 = (k + 2 + 2 * tid) & 31;
            int k3 = (k + 3 + 2 * tid) & 31;
            a0 += sm[OFF_Z + k0] * Wr[k0];
            a1 += sm[OFF_Z + k1] * Wr[k1];
            a2 += sm[OFF_Z + k2] * Wr[k2];
            a3 += sm[OFF_Z + k3] * Wr[k3];
        }
        sm[OFF_VH + tid] = fmaxf((a0 + a1) + (a2 + a3) + sm[OFF_C1B + tid], 0.0f);
    } else if (tid == 16 || tid == 17) {
        const float* Wv = sm + ((tid == 16) ? OFF_MW : OFF_LSW);
        float a0 = 0.f, a1 = 0.f, a2 = 0.f, a3 = 0.f;
        #pragma unroll
        for (int k = 0; k < 32; k += 4) {
            a0 += sm[OFF_Z + k + 0] * Wv[k + 0];
            a1 += sm[OFF_Z + k + 1] * Wv[k + 1];
            a2 += sm[OFF_Z + k + 2] * Wv[k + 2];
            a3 += sm[OFF_Z + k + 3] * Wv[k + 3];
        }
        sm[OFF_SCAL + (tid - 16)] = (a0 + a1) + (a2 + a3) + sm[OFF_SC + (tid - 16)];
    }
    __syncthreads();

    if (tid == 0) {
        float a0 = 0.f, a1 = 0.f;
        #pragma unroll
        for (int k = 0; k < 16; k += 2) {
            a0 += sm[OFF_VH + k]     * sm[OFF_C2W + k];
            a1 += sm[OFF_VH + k + 1] * sm[OFF_C2W + k + 1];
        }
        out[0] = sm[OFF_SCAL + 0];
        out[1] = sm[OFF_SCAL + 1];
        out[2] = a0 + a1 + sm[OFF_SC + 2];
    }
}

extern "C" void kernel_launch(void* const* d_in, const int* in_sizes, int n_in,
                              void* d_out, int out_size) {
    const float* x      = (const float*)d_in[0];
    const float* Wih0   = (const float*)d_in[1];
    const float* bih0   = (const float*)d_in[3];
    const float* bhh0   = (const float*)d_in[4];
    const float* Wih    = (const float*)d_in[5];
    const float* bih    = (const float*)d_in[7];
    const float* bhh    = (const float*)d_in[8];
    const float* fc_w   = (const float*)d_in[9];
    const float* fc_b   = (const float*)d_in[10];
    const float* mean_w = (const float*)d_in[11];
    const float* mean_b = (const float*)d_in[12];
    const float* ls_w   = (const float*)d_in[13];
    const float* ls_b   = (const float*)d_in[14];
    const float* c1_w   = (const float*)d_in[15];
    const float* c1_b   = (const float*)d_in[16];
    const float* c2_w   = (const float*)d_in[17];
    const float* c2_b   = (const float*)d_in[18];

    long long L = in_sizes[0];

    cudaFuncSetAttribute(net_kernel,
                         cudaFuncAttributeMaxDynamicSharedMemorySize, SMEM_BYTES);

    net_kernel<<<1, NT, SMEM_BYTES>>>(x, L, Wih0, bih0, bhh0, Wih, bih, bhh,
                                      fc_w, fc_b, mean_w, mean_b, ls_w, ls_b,
                                      c1_w, c1_b, c2_w, c2_b, (float*)d_out);
}

// round 8
// speedup vs baseline: 1.1301x; 1.1301x over previous
#include <cuda_runtime.h>
#include <cstdint>

// Net_60413009985719 — collapsed net (no recurrence, only x[L-1] matters,
// LSTM f-gate dead). R8 = R4 VERBATIM (best: 10.75us) + two strictly
// subtractive serial-path cuts:
//  1) __expf/__fdividef activations (libm tanhf/expf ~300cyc -> ~80cyc,
//     on the x5 serial act chain)
//  2) layer-0 gates fused into the act thread (one fewer barrier + phase)
// Everything else (TMA 9 bulk copies, rotation matvec, staging, NT=512)
// is byte-identical to R4.

#define H 64
#define ROWS 192          // live gate rows per layer (i, g, o; f is dead)
#define NT 512

// ---- shared layout (float offsets; float4-read regions 16B-aligned) ----
#define OFF_W    0                      // [4][192][64]
#define OFF_FC   (OFF_W + 4*ROWS*H)     // [32][64]
#define OFF_W0   (OFF_FC + 32*H)        // [192]
#define OFF_B0   (OFF_W0 + ROWS)        // [192]
#define OFF_BS   (OFF_B0 + ROWS)        // [4][192]
#define OFF_C1W  (OFF_BS + 4*ROWS)      // [16][32]
#define OFF_C1B  (OFF_C1W + 512)        // [16]
#define OFF_FCB  (OFF_C1B + 16)         // [32]
#define OFF_MW   (OFF_FCB + 32)         // [32]
#define OFF_LSW  (OFF_MW + 32)          // [32]
#define OFF_C2W  (OFF_LSW + 32)         // [16]
#define OFF_SC   (OFF_C2W + 16)         // [3] mean_b, ls_b, c2_b
#define OFF_H    (((OFF_SC + 3) + 3) & ~3)  // [64], 16B-aligned
#define OFF_G    (OFF_H + H)            // [192]
#define OFF_Z    (OFF_G + ROWS)         // [32]
#define OFF_VH   (OFF_Z + 32)           // [16]
#define OFF_SCAL (OFF_VH + 16)          // [2]
#define OFF_MBAR (((OFF_SCAL + 2) + 1) & ~1)   // 8B-aligned; 5 x u64
#define SMEM_FLOATS (OFF_MBAR + 10)
#define SMEM_BYTES  (SMEM_FLOATS * 4)

static_assert((OFF_H % 4) == 0, "h vector must be 16B-aligned");
static_assert((OFF_W % 4) == 0 && (H % 4) == 0, "W rows must be 16B-aligned");
static_assert((OFF_FC % 4) == 0, "fc rows must be 16B-aligned");
static_assert((OFF_MBAR % 2) == 0, "mbarrier must be 8B-aligned");

// fast activations: __expf / __fdividef (~1e-6 composed rel err; budget 1e-3)
__device__ __forceinline__ float fsig(float x) {
    return __fdividef(1.0f, 1.0f + __expf(-x));
}
__device__ __forceinline__ float ftanh(float x) {
    float ax = fabsf(x);
    float e  = __expf(-2.0f * ax);            // in (0,1], no overflow
    float t  = __fdividef(1.0f - e, 1.0f + e);
    return copysignf(t, x);
}

__device__ __forceinline__ void mbar_init(uint32_t addr, uint32_t count) {
    asm volatile("mbarrier.init.shared.b64 [%0], %1;" :: "r"(addr), "r"(count) : "memory");
}
__device__ __forceinline__ void mbar_expect(uint32_t addr, uint32_t bytes) {
    asm volatile("mbarrier.arrive.expect_tx.shared.b64 _, [%0], %1;"
                 :: "r"(addr), "r"(bytes) : "memory");
}
__device__ __forceinline__ void bulk_g2s(uint32_t dst, const void* src,
                                         uint32_t bytes, uint32_t mbar) {
    asm volatile("cp.async.bulk.shared::cta.global.mbarrier::complete_tx::bytes "
                 "[%0], [%1], %2, [%3];"
                 :: "r"(dst), "l"(src), "r"(bytes), "r"(mbar) : "memory");
}
__device__ __forceinline__ void mbar_wait0(uint32_t addr) {
    asm volatile(
        "{\n\t"
        ".reg .pred P;\n\t"
        "WAIT_%=:\n\t"
        "mbarrier.try_wait.parity.acquire.cta.shared::cta.b64 P, [%0], 0, 0x989680;\n\t"
        "@P bra.uni DONE_%=;\n\t"
        "bra.uni WAIT_%=;\n\t"
        "DONE_%=:\n\t"
        "}" :: "r"(addr) : "memory");
}
__device__ __forceinline__ void fence_proxy_async_sc() {
    asm volatile("fence.proxy.async.shared::cta;" ::: "memory");
}

// lstm activation from gate triple -> h value
__device__ __forceinline__ float act3(float gi, float gg, float go) {
    float iv = fsig(gi);
    float gv = ftanh(gg);
    float ov = fsig(go);
    return ov * ftanh(iv * gv);
}

// activation for index idx (0..63) reading gates from sm[OFF_G..]
__device__ __forceinline__ void do_act(float* sm, int idx) {
    sm[OFF_H + idx] = act3(sm[OFF_G + idx], sm[OFF_G + 64 + idx], sm[OFF_G + 128 + idx]);
}

__global__ void __launch_bounds__(NT, 1)
net_kernel(const float* __restrict__ x, long long L,
           const float* __restrict__ Wih0,
           const float* __restrict__ bih0,
           const float* __restrict__ bhh0,
           const float* __restrict__ Wih,
           const float* __restrict__ bih,
           const float* __restrict__ bhh,
           const float* __restrict__ fc_w,
           const float* __restrict__ fc_b,
           const float* __restrict__ mean_w,
           const float* __restrict__ mean_b,
           const float* __restrict__ ls_w,
           const float* __restrict__ ls_b,
           const float* __restrict__ c1_w,
           const float* __restrict__ c1_b,
           const float* __restrict__ c2_w,
           const float* __restrict__ c2_b,
           float* __restrict__ out)
{
    extern __shared__ __align__(16) float sm[];
    const int tid = threadIdx.x;
    const uint32_t smbase = (uint32_t)__cvta_generic_to_shared(sm);
    const uint32_t mbar = smbase + OFF_MBAR * 4;

    // ---- 1) TMA bulk copies for all big weights (thread 0) ----
    if (tid == 0) {
        #pragma unroll
        for (int i = 0; i < 5; ++i) mbar_init(mbar + 8 * i, 1);
        fence_proxy_async_sc();
        #pragma unroll
        for (int l = 0; l < 4; ++l) {
            uint32_t mb = mbar + 8 * l;
            mbar_expect(mb, ROWS * H * 4);
            bulk_g2s(smbase + (OFF_W + (l * ROWS) * H) * 4,
                     Wih + (size_t)l * 256 * H, 64 * H * 4, mb);          // i rows
            bulk_g2s(smbase + (OFF_W + (l * ROWS + 64) * H) * 4,
                     Wih + ((size_t)l * 256 + 128) * H, 128 * H * 4, mb); // g+o rows
        }
        mbar_expect(mbar + 8 * 4, 32 * H * 4);
        bulk_g2s(smbase + OFF_FC * 4, fc_w, 32 * H * 4, mbar + 8 * 4);
    }

    // ---- 2) stage small tensors (plain LDG->STS, overlapped with TMA) ----
    const float xv = x[L - 1];
    if (tid < ROWS) {
        int grow = (tid < 64) ? tid : tid + 64;
        sm[OFF_W0 + tid] = Wih0[grow];
        sm[OFF_B0 + tid] = bih0[grow] + bhh0[grow];
    }
    for (int j = tid; j < 4 * ROWS; j += NT) {
        int l = j / ROWS, r = j - l * ROWS;
        int grow = (r < 64) ? r : r + 64;
        sm[OFF_BS + j] = bih[l * 256 + grow] + bhh[l * 256 + grow];
    }
    for (int j = tid; j < 512; j += NT) sm[OFF_C1W + j] = c1_w[j];
    if (tid < 32) {
        sm[OFF_FCB + tid] = fc_b[tid];
        sm[OFF_MW + tid]  = mean_w[tid];
        sm[OFF_LSW + tid] = ls_w[tid];
    }
    if (tid < 16) {
        sm[OFF_C1B + tid] = c1_b[tid];
        sm[OFF_C2W + tid] = c2_w[tid];
    }
    if (tid == 1) {
        sm[OFF_SC + 0] = mean_b[0];
        sm[OFF_SC + 1] = ls_b[0];
        sm[OFF_SC + 2] = c2_b[0];
    }
    __syncthreads();   // small tensors + mbarrier init visible to all

    // ---- 3) layer 0: gates + activation fused in one phase (no G0 pass) ----
    if (tid < H) {
        float gi = xv * sm[OFF_W0 + tid]       + sm[OFF_B0 + tid];
        float gg = xv * sm[OFF_W0 + 64 + tid]  + sm[OFF_B0 + 64 + tid];
        float go = xv * sm[OFF_W0 + 128 + tid] + sm[OFF_B0 + 128 + tid];
        sm[OFF_H + tid] = act3(gi, gg, go);
    }
    // h0 becomes visible via the sync inside the first loop iteration

    // ---- 4) layers 1..4 from SMEM; wait on per-layer mbarrier ----
    #pragma unroll
    for (int l = 0; l < 4; ++l) {
        mbar_wait0(mbar + 8 * l);
        __syncthreads();       // TMA data + h visible to all
        if (tid < ROWS) {
            const float4* Wr = (const float4*)(sm + OFF_W + (l * ROWS + tid) * H);
            const float4* hv = (const float4*)(sm + OFF_H);
            float acc = sm[OFF_BS + l * ROWS + tid];
            #pragma unroll
            for (int k4 = 0; k4 < 16; ++k4) {
                int kk = (k4 + tid) & 15;       // 16B-granule rotation, conflict-free
                float4 w = Wr[kk];
                float4 h4 = hv[kk];
                acc += w.x * h4.x + w.y * h4.y + w.z * h4.z + w.w * h4.w;
            }
            sm[OFF_G + tid] = acc;
        }
        __syncthreads();
        if (tid < H) do_act(sm, tid);
    }

    mbar_wait0(mbar + 8 * 4);  // fc weights
    __syncthreads();

    // ---- 5) head ----
    if (tid < 32) {
        const float4* Wr = (const float4*)(sm + OFF_FC + tid * H);
        const float4* hv = (const float4*)(sm + OFF_H);
        float acc = sm[OFF_FCB + tid];
        #pragma unroll
        for (int k4 = 0; k4 < 16; ++k4) {
            int kk = (k4 + tid) & 15;
            float4 w = Wr[kk];
            float4 h4 = hv[kk];
            acc += w.x * h4.x + w.y * h4.y + w.z * h4.z + w.w * h4.w;
        }
        sm[OFF_Z + tid] = fmaxf(acc, 0.0f);
    }
    __syncthreads();

    if (tid < 16) {
        const float* Wr = sm + OFF_C1W + tid * 32;
        float acc = sm[OFF_C1B + tid];
        #pragma unroll
        for (int k = 0; k < 32; ++k) {
            int kk = (k + 2 * tid) & 31;
            acc += sm[OFF_Z + kk] * Wr[kk];
        }
        sm[OFF_VH + tid] = fmaxf(acc, 0.0f);
    } else if (tid == 16) {
        float acc = sm[OFF_SC + 0];
        #pragma unroll
        for (int k = 0; k < 32; ++k) acc += sm[OFF_Z + k] * sm[OFF_MW + k];
        sm[OFF_SCAL + 0] = acc;
    } else if (tid == 17) {
        float acc = sm[OFF_SC + 1];
        #pragma unroll
        for (int k = 0; k < 32; ++k) acc += sm[OFF_Z + k] * sm[OFF_LSW + k];
        sm[OFF_SCAL + 1] = acc;
    }
    __syncthreads();

    if (tid == 0) {
        float acc = sm[OFF_SC + 2];
        #pragma unroll
        for (int k = 0; k < 16; ++k) acc += sm[OFF_VH + k] * sm[OFF_C2W + k];
        out[0] = sm[OFF_SCAL + 0];
        out[1] = sm[OFF_SCAL + 1];
        out[2] = acc;
    }
}

extern "C" void kernel_launch(void* const* d_in, const int* in_sizes, int n_in,
                              void* d_out, int out_size) {
    const float* x      = (const float*)d_in[0];
    const float* Wih0   = (const float*)d_in[1];
    const float* bih0   = (const float*)d_in[3];
    const float* bhh0   = (const float*)d_in[4];
    const float* Wih    = (const float*)d_in[5];
    const float* bih    = (const float*)d_in[7];
    const float* bhh    = (const float*)d_in[8];
    const float* fc_w   = (const float*)d_in[9];
    const float* fc_b   = (const float*)d_in[10];
    const float* mean_w = (const float*)d_in[11];
    const float* mean_b = (const float*)d_in[12];
    const float* ls_w   = (const float*)d_in[13];
    const float* ls_b   = (const float*)d_in[14];
    const float* c1_w   = (const float*)d_in[15];
    const float* c1_b   = (const float*)d_in[16];
    const float* c2_w   = (const float*)d_in[17];
    const float* c2_b   = (const float*)d_in[18];

    long long L = in_sizes[0];

    cudaFuncSetAttribute(net_kernel,
                         cudaFuncAttributeMaxDynamicSharedMemorySize, SMEM_BYTES);

    net_kernel<<<1, NT, SMEM_BYTES>>>(x, L, Wih0, bih0, bhh0, Wih, bih, bhh,
                                      fc_w, fc_b, mean_w, mean_b, ls_w, ls_b,
                                      c1_w, c1_b, c2_w, c2_b, (float*)d_out);
}

// round 10
// speedup vs baseline: 1.1777x; 1.0422x over previous
#include <cuda_runtime.h>
#include <cstdint>

// Net_60413009985719 — collapsed net (no recurrence, only x[L-1] matters,
// LSTM f-gate dead). R9: attack the matvec SMEM crossbar (biggest remaining
// cycle block, ~3100 cyc):
//  - W rows PADDED to 68 floats -> uniform-index LDS.128 conflict-free
//  - h reads become uniform -> smem BROADCAST (4 crossbar cyc -> 1)
//  - padded fill via cp.async/LDGSTS (strided dst; ~800 cyc issue total,
//    overlapped; mechanism proven in R2) with per-layer commit groups
//  - R8's fast activations + fused layer-0 kept (subtractive)

#define H 64
#define ROWS 192          // live gate rows per layer (i, g, o; f is dead)
#define WPAD 68           // padded row stride (272B): bank = 4(r+j) mod 32
#define NT 512

// ---- shared layout (float offsets; float4 regions 16B-aligned) ----
#define OFF_W    0                        // [4][192][68] padded rows
#define OFF_FC   (OFF_W + 4*ROWS*WPAD)    // [32][68] padded rows
#define OFF_W0   (OFF_FC + 32*WPAD)       // [192]
#define OFF_B0   (OFF_W0 + ROWS)          // [192]
#define OFF_BS   (OFF_B0 + ROWS)          // [4][192]
#define OFF_C1W  (OFF_BS + 4*ROWS)        // [16][32]
#define OFF_C1B  (OFF_C1W + 512)          // [16]
#define OFF_FCB  (OFF_C1B + 16)           // [32]
#define OFF_MW   (OFF_FCB + 32)           // [32]
#define OFF_LSW  (OFF_MW + 32)            // [32]
#define OFF_C2W  (OFF_LSW + 32)           // [16]
#define OFF_SC   (OFF_C2W + 16)           // [3] mean_b, ls_b, c2_b
#define OFF_H    (((OFF_SC + 3) + 3) & ~3)    // [64], 16B-aligned
#define OFF_G    (OFF_H + H)              // [192]
#define OFF_Z    (OFF_G + ROWS)           // [32]
#define OFF_VH   (OFF_Z + 32)             // [16]
#define OFF_SCAL (OFF_VH + 16)            // [2]
#define SMEM_FLOATS (OFF_SCAL + 2)
#define SMEM_BYTES  (SMEM_FLOATS * 4)

static_assert(SMEM_BYTES <= 232448, "exceeds sm_100a dynamic smem cap");
static_assert((WPAD % 4) == 0, "padded stride must be 16B-aligned");
static_assert((OFF_H % 4) == 0, "h vector must be 16B-aligned");
static_assert((OFF_W % 4) == 0 && (OFF_FC % 4) == 0, "W/fc must be 16B-aligned");

// fast activations: __expf / __fdividef (~1e-6 composed rel err; budget 1e-3)
__device__ __forceinline__ float fsig(float x) {
    return __fdividef(1.0f, 1.0f + __expf(-x));
}
__device__ __forceinline__ float ftanh(float x) {
    float ax = fabsf(x);
    float e  = __expf(-2.0f * ax);            // in (0,1], no overflow
    float t  = __fdividef(1.0f - e, 1.0f + e);
    return copysignf(t, x);
}
__device__ __forceinline__ float act3(float gi, float gg, float go) {
    float iv = fsig(gi);
    float gv = ftanh(gg);
    float ov = fsig(go);
    return ov * ftanh(iv * gv);
}
__device__ __forceinline__ void do_act(float* sm, int idx) {
    sm[OFF_H + idx] = act3(sm[OFF_G + idx], sm[OFF_G + 64 + idx], sm[OFF_G + 128 + idx]);
}

__device__ __forceinline__ void cp16(uint32_t dst_smem, const void* src) {
    asm volatile("cp.async.cg.shared.global [%0], [%1], 16;" :: "r"(dst_smem), "l"(src));
}
__device__ __forceinline__ void cp_commit() {
    asm volatile("cp.async.commit_group;");
}
template <int N>
__device__ __forceinline__ void cp_wait() {
    asm volatile("cp.async.wait_group %0;" :: "n"(N));
}

__global__ void __launch_bounds__(NT, 1)
net_kernel(const float* __restrict__ x, long long L,
           const float* __restrict__ Wih0,
           const float* __restrict__ bih0,
           const float* __restrict__ bhh0,
           const float* __restrict__ Wih,
           const float* __restrict__ bih,
           const float* __restrict__ bhh,
           const float* __restrict__ fc_w,
           const float* __restrict__ fc_b,
           const float* __restrict__ mean_w,
           const float* __restrict__ mean_b,
           const float* __restrict__ ls_w,
           const float* __restrict__ ls_b,
           const float* __restrict__ c1_w,
           const float* __restrict__ c1_b,
           const float* __restrict__ c2_w,
           const float* __restrict__ c2_b,
           float* __restrict__ out)
{
    extern __shared__ __align__(16) float sm[];
    const int tid = threadIdx.x;
    const uint32_t smbase = (uint32_t)__cvta_generic_to_shared(sm);

    // ---- 1) stream big weights into PADDED rows, one commit group/layer ----
    // shared row r (0..191) <-> gmem gate row: i:[0,64) g+o:[128,256)
    #pragma unroll
    for (int l = 0; l < 4; ++l) {
        for (int c = tid; c < ROWS * 16; c += NT) {       // 16B chunks
            int r = c >> 4, ch = c & 15;
            int grow = (r < 64) ? r : r + 64;
            uint32_t dst = smbase + (uint32_t)((OFF_W + (l * ROWS + r) * WPAD + ch * 4) * 4);
            cp16(dst, Wih + ((size_t)l * 256 + grow) * H + ch * 4);
        }
        cp_commit();
    }
    for (int c = tid; c < 32 * 16; c += NT) {             // fc, padded too
        int r = c >> 4, ch = c & 15;
        cp16(smbase + (uint32_t)((OFF_FC + r * WPAD + ch * 4) * 4), fc_w + r * H + ch * 4);
    }
    cp_commit();

    // ---- 2) stage small tensors (plain LDG->STS, overlapped) ----
    const float xv = x[L - 1];
    if (tid < ROWS) {
        int grow = (tid < 64) ? tid : tid + 64;
        sm[OFF_W0 + tid] = Wih0[grow];
        sm[OFF_B0 + tid] = bih0[grow] + bhh0[grow];
    }
    for (int j = tid; j < 4 * ROWS; j += NT) {
        int l = j / ROWS, r = j - l * ROWS;
        int grow = (r < 64) ? r : r + 64;
        sm[OFF_BS + j] = bih[l * 256 + grow] + bhh[l * 256 + grow];
    }
    for (int j = tid; j < 512; j += NT) sm[OFF_C1W + j] = c1_w[j];
    if (tid < 32) {
        sm[OFF_FCB + tid] = fc_b[tid];
        sm[OFF_MW + tid]  = mean_w[tid];
        sm[OFF_LSW + tid] = ls_w[tid];
    }
    if (tid < 16) {
        sm[OFF_C1B + tid] = c1_b[tid];
        sm[OFF_C2W + tid] = c2_w[tid];
    }
    if (tid == 1) {
        sm[OFF_SC + 0] = mean_b[0];
        sm[OFF_SC + 1] = ls_b[0];
        sm[OFF_SC + 2] = c2_b[0];
    }
    __syncthreads();   // staging visible

    // ---- 3) layer 0: gates + activation fused (h0 visible via loop sync) ----
    if (tid < H) {
        float gi = xv * sm[OFF_W0 + tid]       + sm[OFF_B0 + tid];
        float gg = xv * sm[OFF_W0 + 64 + tid]  + sm[OFF_B0 + 64 + tid];
        float go = xv * sm[OFF_W0 + 128 + tid] + sm[OFF_B0 + 128 + tid];
        sm[OFF_H + tid] = act3(gi, gg, go);
    }

    // ---- 4) layers 1..4: uniform-index matvec (W conflict-free via pad,
    //         h broadcast), wait only for the needed commit group ----
    #pragma unroll
    for (int l = 0; l < 4; ++l) {
        switch (l) {
            case 0: cp_wait<4>(); break;
            case 1: cp_wait<3>(); break;
            case 2: cp_wait<2>(); break;
            case 3: cp_wait<1>(); break;
        }
        __syncthreads();       // copies + h visible to all
        if (tid < ROWS) {
            const float4* Wr = (const float4*)(sm + OFF_W + (l * ROWS + tid) * WPAD);
            const float4* hv = (const float4*)(sm + OFF_H);
            float a0 = 0.f, a1 = 0.f, a2 = 0.f, a3 = 0.f;
            #pragma unroll
            for (int j = 0; j < 16; j += 4) {
                float4 w0 = Wr[j + 0], h0 = hv[j + 0];   // uniform j: h broadcast
                float4 w1 = Wr[j + 1], h1 = hv[j + 1];
                float4 w2 = Wr[j + 2], h2 = hv[j + 2];
                float4 w3 = Wr[j + 3], h3 = hv[j + 3];
                a0 += w0.x * h0.x + w0.y * h0.y + w0.z * h0.z + w0.w * h0.w;
                a1 += w1.x * h1.x + w1.y * h1.y + w1.z * h1.z + w1.w * h1.w;
                a2 += w2.x * h2.x + w2.y * h2.y + w2.z * h2.z + w2.w * h2.w;
                a3 += w3.x * h3.x + w3.y * h3.y + w3.z * h3.z + w3.w * h3.w;
            }
            sm[OFF_G + tid] = (a0 + a1) + (a2 + a3) + sm[OFF_BS + l * ROWS + tid];
        }
        __syncthreads();
        if (tid < H) do_act(sm, tid);
    }

    cp_wait<0>();              // fc weights
    __syncthreads();

    // ---- 5) head: z = relu(fc), padded rows, uniform index ----
    if (tid < 32) {
        const float4* Wr = (const float4*)(sm + OFF_FC + tid * WPAD);
        const float4* hv = (const float4*)(sm + OFF_H);
        float a0 = 0.f, a1 = 0.f, a2 = 0.f, a3 = 0.f;
        #pragma unroll
        for (int j = 0; j < 16; j += 4) {
            float4 w0 = Wr[j + 0], h0 = hv[j + 0];
            float4 w1 = Wr[j + 1], h1 = hv[j + 1];
            float4 w2 = Wr[j + 2], h2 = hv[j + 2];
            float4 w3 = Wr[j + 3], h3 = hv[j + 3];
            a0 += w0.x * h0.x + w0.y * h0.y + w0.z * h0.z + w0.w * h0.w;
            a1 += w1.x * h1.x + w1.y * h1.y + w1.z * h1.z + w1.w * h1.w;
            a2 += w2.x * h2.x + w2.y * h2.y + w2.z * h2.z + w2.w * h2.w;
            a3 += w3.x * h3.x + w3.y * h3.y + w3.z * h3.z + w3.w * h3.w;
        }
        sm[OFF_Z + tid] = fmaxf((a0 + a1) + (a2 + a3) + sm[OFF_FCB + tid], 0.0f);
    }
    __syncthreads();

    // ---- 6) tiny heads ----
    if (tid < 16) {
        const float* Wr = sm + OFF_C1W + tid * 32;
        float a0 = 0.f, a1 = 0.f, a2 = 0.f, a3 = 0.f;
        #pragma unroll
        for (int k = 0; k < 32; k += 4) {
            int k0 = (k + 0 + 2 * tid) & 31;
            int k1 = (k + 1 + 2 * tid) & 31;
            int k2 = (k + 2 + 2 * tid) & 31;
            int k3 = (k + 3 + 2 * tid) & 31;
            a0 += sm[OFF_Z + k0] * Wr[k0];
            a1 += sm[OFF_Z + k1] * Wr[k1];
            a2 += sm[OFF_Z + k2] * Wr[k2];
            a3 += sm[OFF_Z + k3] * Wr[k3];
        }
        sm[OFF_VH + tid] = fmaxf((a0 + a1) + (a2 + a3) + sm[OFF_C1B + tid], 0.0f);
    } else if (tid == 16 || tid == 17) {
        const float* Wv = sm + ((tid == 16) ? OFF_MW : OFF_LSW);
        float a0 = 0.f, a1 = 0.f, a2 = 0.f, a3 = 0.f;
        #pragma unroll
        for (int k = 0; k < 32; k += 4) {
            a0 += sm[OFF_Z + k + 0] * Wv[k + 0];
            a1 += sm[OFF_Z + k + 1] * Wv[k + 1];
            a2 += sm[OFF_Z + k + 2] * Wv[k + 2];
            a3 += sm[OFF_Z + k + 3] * Wv[k + 3];
        }
        sm[OFF_SCAL + (tid - 16)] = (a0 + a1) + (a2 + a3) + sm[OFF_SC + (tid - 16)];
    }
    __syncthreads();

    if (tid == 0) {
        float a0 = 0.f, a1 = 0.f;
        #pragma unroll
        for (int k = 0; k < 16; k += 2) {
            a0 += sm[OFF_VH + k]     * sm[OFF_C2W + k];
            a1 += sm[OFF_VH + k + 1] * sm[OFF_C2W + k + 1];
        }
        out[0] = sm[OFF_SCAL + 0];
        out[1] = sm[OFF_SCAL + 1];
        out[2] = a0 + a1 + sm[OFF_SC + 2];
    }
}

extern "C" void kernel_launch(void* const* d_in, const int* in_sizes, int n_in,
                              void* d_out, int out_size) {
    const float* x      = (const float*)d_in[0];
    const float* Wih0   = (const float*)d_in[1];
    const float* bih0   = (const float*)d_in[3];
    const float* bhh0   = (const float*)d_in[4];
    const float* Wih    = (const float*)d_in[5];
    const float* bih    = (const float*)d_in[7];
    const float* bhh    = (const float*)d_in[8];
    const float* fc_w   = (const float*)d_in[9];
    const float* fc_b   = (const float*)d_in[10];
    const float* mean_w = (const float*)d_in[11];
    const float* mean_b = (const float*)d_in[12];
    const float* ls_w   = (const float*)d_in[13];
    const float* ls_b   = (const float*)d_in[14];
    const float* c1_w   = (const float*)d_in[15];
    const float* c1_b   = (const float*)d_in[16];
    const float* c2_w   = (const float*)d_in[17];
    const float* c2_b   = (const float*)d_in[18];

    long long L = in_sizes[0];

    cudaFuncSetAttribute(net_kernel,
                         cudaFuncAttributeMaxDynamicSharedMemorySize, SMEM_BYTES);

    net_kernel<<<1, NT, SMEM_BYTES>>>(x, L, Wih0, bih0, bhh0, Wih, bih, bhh,
                                      fc_w, fc_b, mean_w, mean_b, ls_w, ls_b,
                                      c1_w, c1_b, c2_w, c2_b, (float*)d_out);
}